// round 4
// baseline (speedup 1.0000x reference)
#include <cuda_runtime.h>
#include <stdint.h>

#define ROW_N 2048
#define K_SEL 1024u
#define NT    256

__global__ __launch_bounds__(NT, 8) void kta_kernel(const float* __restrict__ in,
                                                    float* __restrict__ out) {
    __shared__ float    s_cand[ROW_N];   // 8 KB worst-case (fallback level 2)
    __shared__ uint32_t s_w[8];
    __shared__ uint32_t s_cnt;
    __shared__ float    s_T;

    const int t    = threadIdx.x;
    const int lane = t & 31;
    const int wid  = t >> 5;
    const size_t base = (size_t)blockIdx.x * ROW_N;
    const float4* in4  = (const float4*)(in  + base);
    float4*       out4 = (float4*)(out + base);

    // ---- load row into registers ----
    float f[8];
    {
        float4 a = in4[t], b = in4[t + NT];
        f[0]=a.x; f[1]=a.y; f[2]=a.z; f[3]=a.w;
        f[4]=b.x; f[5]=b.y; f[6]=b.z; f[7]=b.w;
    }

    if (t == 0) s_cnt = 0;
    __syncthreads();

    const float NEG_INF = __uint_as_float(0xFF800000u);
    const float POS_INF = __uint_as_float(0x7F800000u);

    uint32_t c_lo = 0, C = 0, k2 = 0;

#pragma unroll
    for (int lvl = 0; lvl < 3; lvl++) {
        const float lo = (lvl == 0) ? -0.10f : ((lvl == 1) ? -0.60f : NEG_INF);
        const float hi = (lvl == 0) ?  0.10f : ((lvl == 1) ?  0.60f : POS_INF);

        if (lvl > 0) {               // rare fallback: reset candidate buffer
            __syncthreads();
            if (t == 0) s_cnt = 0;
            __syncthreads();
        }

        // count below lo + compact candidates in [lo, hi) in one register pass
        uint32_t myclo = 0;
#pragma unroll
        for (int e = 0; e < 8; e++) {
            bool plo = f[e] < lo;
            bool pin = !plo && !(f[e] >= hi);
            myclo += plo ? 1u : 0u;
            uint32_t m = __ballot_sync(0xFFFFFFFFu, pin);
            if (m) {
                uint32_t ldr  = __ffs(m) - 1u;
                uint32_t bpos = 0;
                if (lane == ldr) bpos = atomicAdd(&s_cnt, (uint32_t)__popc(m));
                bpos = __shfl_sync(0xFFFFFFFFu, bpos, ldr);
                if (pin) s_cand[bpos + __popc(m & ((1u << lane) - 1u))] = f[e];
            }
        }
        myclo = __reduce_add_sync(0xFFFFFFFFu, myclo);
        if (lane == 0) s_w[wid] = myclo;
        __syncthreads();

        c_lo = 0;
#pragma unroll
        for (int w = 0; w < 8; w++) c_lo += s_w[w];
        C = s_cnt;

        if (c_lo < K_SEL && (K_SEL - c_lo) <= C) { k2 = K_SEL - c_lo; break; }
    }

    // ---- exact rank-select: T = k2-th smallest of the C candidates ----
    for (uint32_t i = t; i < C; i += NT) {
        float v = s_cand[i];
        uint32_t less = 0, leq = 0;
        for (uint32_t j = 0; j < C; j++) {
            float c = s_cand[j];               // broadcast LDS
            less += (c <  v) ? 1u : 0u;
            leq  += (c <= v) ? 1u : 0u;
        }
        if (less < k2 && k2 <= leq) s_T = v;   // dup-safe
    }
    __syncthreads();
    const float T = s_T;

    // ---- output from registers: zero everything <= T ----
    float4 o0, o1;
    o0.x = (f[0] <= T) ? 0.0f : f[0];
    o0.y = (f[1] <= T) ? 0.0f : f[1];
    o0.z = (f[2] <= T) ? 0.0f : f[2];
    o0.w = (f[3] <= T) ? 0.0f : f[3];
    o1.x = (f[4] <= T) ? 0.0f : f[4];
    o1.y = (f[5] <= T) ? 0.0f : f[5];
    o1.z = (f[6] <= T) ? 0.0f : f[6];
    o1.w = (f[7] <= T) ? 0.0f : f[7];
    out4[t]      = o0;
    out4[t + NT] = o1;
}

extern "C" void kernel_launch(void* const* d_in, const int* in_sizes, int n_in,
                              void* d_out, int out_size) {
    const float* in = (const float*)d_in[0];
    float* out = (float*)d_out;
    int rows = in_sizes[0] / ROW_N;
    kta_kernel<<<rows, NT>>>(in, out);
}

// round 5
// speedup vs baseline: 2.9072x; 2.9072x over previous
#include <cuda_runtime.h>
#include <stdint.h>

#define ROW_N 2048
#define K_SEL 1024u
#define NT    256
#define FULLM 0xFFFFFFFFu

__device__ __forceinline__ uint32_t f2u_ord(float x) {
    uint32_t b = __float_as_uint(x);
    uint32_t m = (uint32_t)(((int32_t)b) >> 31) | 0x80000000u;
    return b ^ m;
}
__device__ __forceinline__ float u2f_ord(uint32_t u) {
    uint32_t m = (uint32_t)(((int32_t)(~u)) >> 31) | 0x80000000u;
    return __uint_as_float(u ^ m);
}
__device__ __forceinline__ uint32_t bin_of(uint32_t u, int lvl, float lo, float scale) {
    if (lvl == 2) return u >> 24;                    // monotone exponent-byte bins
    float v = u2f_ord(u);
    int b = __float2int_rd((v - lo) * scale);
    return (uint32_t)max(0, min(b, 255));
}

__global__ __launch_bounds__(NT, 8) void kta_kernel(const float* __restrict__ in,
                                                    float* __restrict__ out) {
    __shared__ uint32_t s_cand[ROW_N];   // 8 KB (worst-case fallback)
    __shared__ uint32_t s_hist[256];     // 1 KB
    __shared__ uint32_t s_w[8];
    __shared__ uint32_t s_cnt;
    __shared__ uint32_t s_sel[2];
    __shared__ uint32_t s_minu, s_c;

    const int t    = threadIdx.x;
    const int lane = t & 31;
    const int wid  = t >> 5;
    const size_t base = (size_t)blockIdx.x * ROW_N;
    const float4* in4  = (const float4*)(in  + base);
    float4*       out4 = (float4*)(out + base);

    // ---- load row into registers ----
    float f[8];
    {
        float4 a = in4[t], b4 = in4[t + NT];
        f[0]=a.x;  f[1]=a.y;  f[2]=a.z;  f[3]=a.w;
        f[4]=b4.x; f[5]=b4.y; f[6]=b4.z; f[7]=b4.w;
    }

    const float NEG_INF = __uint_as_float(0xFF800000u);
    const float POS_INF = __uint_as_float(0x7F800000u);

    // ---- adaptive bracket: count-below + compact candidates (1 atomic/warp) ----
    uint32_t k2 = 0, C = 0;
    int   lvl   = 0;
    float lo_f  = 0.0f, scale_f = 0.0f;

    for (lvl = 0; lvl < 3; lvl++) {
        const float lo = (lvl == 0) ? -0.10f : ((lvl == 1) ? -0.60f : NEG_INF);
        const float hi = (lvl == 0) ?  0.10f : ((lvl == 1) ?  0.60f : POS_INF);

        __syncthreads();
        if (t == 0) s_cnt = 0;
        __syncthreads();

        bool pin[8];
        int nc = 0;
        uint32_t myclo = 0;
#pragma unroll
        for (int e = 0; e < 8; e++) {
            myclo  += (f[e] < lo) ? 1u : 0u;
            pin[e]  = (f[e] >= lo) && (f[e] < hi);
            nc     += pin[e] ? 1 : 0;
        }
        // warp exclusive scan of candidate counts
        uint32_t inc = (uint32_t)nc;
#pragma unroll
        for (int o = 1; o < 32; o <<= 1) {
            uint32_t v = __shfl_up_sync(FULLM, inc, o);
            if (lane >= o) inc += v;
        }
        uint32_t excl  = inc - (uint32_t)nc;
        uint32_t wbase = 0;
        if (lane == 31) wbase = atomicAdd(&s_cnt, inc);
        wbase = __shfl_sync(FULLM, wbase, 31);
        uint32_t pos = wbase + excl;
#pragma unroll
        for (int e = 0; e < 8; e++)
            if (pin[e]) s_cand[pos++] = f2u_ord(f[e]);

        myclo = __reduce_add_sync(FULLM, myclo);
        if (lane == 0) s_w[wid] = myclo;
        __syncthreads();

        uint32_t clo = 0;
#pragma unroll
        for (int w = 0; w < 8; w++) clo += s_w[w];
        C = s_cnt;

        if (clo < K_SEL && (K_SEL - clo) <= C) {
            k2      = K_SEL - clo;
            lo_f    = lo;
            scale_f = 256.0f / (hi - lo);
            break;
        }
    }
    if (lvl > 2) lvl = 2;   // unreachable; keeps lvl defined

    // ---- 256-bin histogram over candidates only ----
    s_hist[t] = 0;
    __syncthreads();
    for (uint32_t i = t; i < C; i += NT)
        atomicAdd(&s_hist[bin_of(s_cand[i], lvl, lo_f, scale_f)], 1u);
    __syncthreads();

    // ---- scan 256 bins, locate crossing bin ----
    uint32_t cnt  = s_hist[t];
    uint32_t inc2 = cnt;
#pragma unroll
    for (int o = 1; o < 32; o <<= 1) {
        uint32_t v = __shfl_up_sync(FULLM, inc2, o);
        if (lane >= o) inc2 += v;
    }
    if (lane == 31) s_w[wid] = inc2;
    __syncthreads();
    if (t == 0) {
        uint32_t run = 0;
#pragma unroll
        for (int w = 0; w < 8; w++) { uint32_t x = s_w[w]; s_w[w] = run; run += x; }
    }
    __syncthreads();
    inc2 += s_w[wid];
    uint32_t exc = inc2 - cnt;
    if (exc < k2 && k2 <= inc2) { s_sel[0] = (uint32_t)t; s_sel[1] = exc; }
    __syncthreads();

    const uint32_t bsel = s_sel[0];
    uint32_t rem = k2 - s_sel[1];      // rank within bin (1-based); expected bin size ~0.64

    // ---- exact k-th value: min-extraction within bin (expected 1 iteration) ----
    uint32_t curnext = 0, Tu = 0;
    while (true) {
        if (t == 0) { s_minu = FULLM; s_c = 0; }
        __syncthreads();
        for (uint32_t i = t; i < C; i += NT) {
            uint32_t uu = s_cand[i];
            if (uu >= curnext && bin_of(uu, lvl, lo_f, scale_f) == bsel)
                atomicMin(&s_minu, uu);
        }
        __syncthreads();
        uint32_t m = s_minu;
        if (m == FULLM) { Tu = curnext ? curnext - 1u : 0u; break; }  // safety guard
        for (uint32_t i = t; i < C; i += NT)
            if (s_cand[i] == m) atomicAdd(&s_c, 1u);
        __syncthreads();
        uint32_t dup = s_c;
        if (dup >= rem) { Tu = m; break; }
        rem    -= dup;
        curnext = m + 1u;
        __syncthreads();
    }
    const float T = u2f_ord(Tu);

    // ---- output from registers: zero everything <= T ----
    float4 o0, o1;
    o0.x = (f[0] <= T) ? 0.0f : f[0];
    o0.y = (f[1] <= T) ? 0.0f : f[1];
    o0.z = (f[2] <= T) ? 0.0f : f[2];
    o0.w = (f[3] <= T) ? 0.0f : f[3];
    o1.x = (f[4] <= T) ? 0.0f : f[4];
    o1.y = (f[5] <= T) ? 0.0f : f[5];
    o1.z = (f[6] <= T) ? 0.0f : f[6];
    o1.w = (f[7] <= T) ? 0.0f : f[7];
    out4[t]      = o0;
    out4[t + NT] = o1;
}

extern "C" void kernel_launch(void* const* d_in, const int* in_sizes, int n_in,
                              void* d_out, int out_size) {
    const float* in = (const float*)d_in[0];
    float* out = (float*)d_out;
    int rows = in_sizes[0] / ROW_N;
    kta_kernel<<<rows, NT>>>(in, out);
}

// round 6
// speedup vs baseline: 3.4653x; 1.1920x over previous
#include <cuda_runtime.h>
#include <stdint.h>

#define ROW_N 2048
#define K_SEL 1024
#define NT    256
#define FULLM 0xFFFFFFFFu

__device__ __forceinline__ uint32_t f2u_ord(float x) {
    uint32_t b = __float_as_uint(x);
    uint32_t m = (uint32_t)(((int32_t)b) >> 31) | 0x80000000u;
    return b ^ m;
}

__global__ __launch_bounds__(NT, 8) void kta_kernel(const float* __restrict__ in,
                                                    float* __restrict__ out) {
    __shared__ uint32_t s_hist[256];
    __shared__ float    s_cand[ROW_N];   // worst-case capacity (degenerate data)
    __shared__ uint32_t s_w[8];          // count-below partials
    __shared__ uint32_t s_w2[8];         // scan partials
    __shared__ uint32_t s_sel[2];        // {crossing bin, exclusive count}
    __shared__ uint32_t s_cnt;
    __shared__ float    s_T;

    const int t    = threadIdx.x;
    const int lane = t & 31;
    const int wid  = t >> 5;
    const size_t base = (size_t)blockIdx.x * ROW_N;
    const float4* in4  = (const float4*)(in  + base);
    float4*       out4 = (float4*)(out + base);

    // ---- load row into registers ----
    float f[8];
    {
        float4 a = in4[t], b4 = in4[t + NT];
        f[0]=a.x;  f[1]=a.y;  f[2]=a.z;  f[3]=a.w;
        f[4]=b4.x; f[5]=b4.y; f[6]=b4.z; f[7]=b4.w;
    }

    int   sel_lvl = 2;
    float sel_lo = 0.f, sel_scale = 0.f;
    int   bsel = 0, rem = 0;

    for (int lvl = 0; lvl < 3; lvl++) {
        const float lo    = (lvl == 0) ? -0.10f  : -0.60f;
        const float scale = (lvl == 0) ? 1280.0f : (256.0f / 1.2f);

        s_hist[t] = 0;
        if (t == 0) { s_sel[0] = FULLM; s_cnt = 0; }
        __syncthreads();

        // ---- fused bracket + histogram pass (registers -> predicated atomics) ----
        uint32_t myclo = 0;
#pragma unroll
        for (int e = 0; e < 8; e++) {
            int b;
            if (lvl < 2) {
                b = __float2int_rd((f[e] - lo) * scale);
                myclo += (b < 0) ? 1u : 0u;
                if ((unsigned)b < 256u) atomicAdd(&s_hist[b], 1u);
            } else {
                b = (int)(f2u_ord(f[e]) >> 24);
                atomicAdd(&s_hist[b], 1u);
            }
        }
        myclo = __reduce_add_sync(FULLM, myclo);
        if (lane == 0) s_w[wid] = myclo;
        __syncthreads();

        int clo = 0;
#pragma unroll
        for (int w = 0; w < 8; w++) clo += (int)s_w[w];
        const int k2 = K_SEL - clo;

        // ---- scan 256 bins, locate crossing ----
        uint32_t cnt = s_hist[t];
        uint32_t inc = cnt;
#pragma unroll
        for (int o = 1; o < 32; o <<= 1) {
            uint32_t v = __shfl_up_sync(FULLM, inc, o);
            if (lane >= o) inc += v;
        }
        if (lane == 31) s_w2[wid] = inc;
        __syncthreads();
        if (t == 0) {
            uint32_t run = 0;
#pragma unroll
            for (int w = 0; w < 8; w++) { uint32_t x = s_w2[w]; s_w2[w] = run; run += x; }
        }
        __syncthreads();
        inc += s_w2[wid];
        int exc = (int)(inc - cnt);
        if (exc < k2 && k2 <= (int)inc) { s_sel[0] = (uint32_t)t; s_sel[1] = (uint32_t)exc; }
        __syncthreads();

        if (s_sel[0] != FULLM) {
            sel_lvl   = lvl;
            sel_lo    = lo;
            sel_scale = scale;
            bsel      = (int)s_sel[0];
            rem       = k2 - (int)s_sel[1];   // 1-based rank within bin
            break;
        }
        __syncthreads();   // protect s_hist reuse on fallback
    }

    // ---- gather elements of the crossing bin (expected <1 per CTA) ----
#pragma unroll
    for (int e = 0; e < 8; e++) {
        int b;
        if (sel_lvl < 2) b = __float2int_rd((f[e] - sel_lo) * sel_scale);
        else             b = (int)(f2u_ord(f[e]) >> 24);
        if (b == bsel) {
            uint32_t pos = atomicAdd(&s_cnt, 1u);
            s_cand[pos] = f[e];
        }
    }
    __syncthreads();
    const int B = (int)s_cnt;

    // ---- exact rank among the B gathered values (B tiny; worst case bounded) ----
    for (int i = t; i < B; i += NT) {
        float v = s_cand[i];
        int less = 0, leq = 0;
        for (int j = 0; j < B; j++) {
            float c = s_cand[j];
            less += (c <  v) ? 1 : 0;
            leq  += (c <= v) ? 1 : 0;
        }
        if (less < rem && rem <= leq) s_T = v;
    }
    __syncthreads();
    const float T = s_T;

    // ---- output from registers: zero everything <= T ----
    float4 o0, o1;
    o0.x = (f[0] <= T) ? 0.0f : f[0];
    o0.y = (f[1] <= T) ? 0.0f : f[1];
    o0.z = (f[2] <= T) ? 0.0f : f[2];
    o0.w = (f[3] <= T) ? 0.0f : f[3];
    o1.x = (f[4] <= T) ? 0.0f : f[4];
    o1.y = (f[5] <= T) ? 0.0f : f[5];
    o1.z = (f[6] <= T) ? 0.0f : f[6];
    o1.w = (f[7] <= T) ? 0.0f : f[7];
    out4[t]      = o0;
    out4[t + NT] = o1;
}

extern "C" void kernel_launch(void* const* d_in, const int* in_sizes, int n_in,
                              void* d_out, int out_size) {
    const float* in = (const float*)d_in[0];
    float* out = (float*)d_out;
    int rows = in_sizes[0] / ROW_N;
    kta_kernel<<<rows, NT>>>(in, out);
}